// round 15
// baseline (speedup 1.0000x reference)
#include <cuda_runtime.h>
#include <cuda_bf16.h>
#include <cuda_fp16.h>
#include <cstdint>
#include <math.h>

#define N_NODES 8192
#define F_IN    256
#define F_OUT   128
#define NB      136            // GEMM N: 128 feats + den col(128) + 7 zero pad
#define JSPLIT  2
#define JCHUNK  (N_NODES / JSPLIT)   // 4096
#define NTILES  (JCHUNK / 64)        // 64 k-tiles per CTA
#define MROWS   128                  // rows per CTA

// ------------------------------ device scratch ------------------------------
__device__ float    g_Wh[N_NODES * F_OUT];        // 4 MB
__device__ float    g_F[N_NODES], g_Fp[N_NODES];  // e^y, e^{0.2y}
__device__ __half   g_yhf[N_NODES];               // fp16(y_j)
__device__ uint32_t g_nx2[N_NODES];               // {fp16(-x_i)} x2
__device__ uint32_t g_Ex2[N_NODES];               // {fp16(e^{x_i})} x2
__device__ uint32_t g_Epx2[N_NODES];              // {fp16(e^{0.2 x_i})} x2
// B planes [pl][NB][8192] fp16; pl: 0 = B1 = F*Wh, 1 = B0 = Fp*Wh
__device__ __half   g_B[2 * NB * N_NODES];        // 4.5 MB
__device__ float    g_pnum[JSPLIT][N_NODES][F_OUT];  // 8 MB partial numerators
__device__ float    g_pden[JSPLIT][N_NODES];

// ------------------------------ asm helpers ---------------------------------
__device__ __forceinline__ uint32_t smem_u32(const void* p) {
    uint32_t a;
    asm("{ .reg .u64 t; cvta.to.shared.u64 t, %1; cvt.u32.u64 %0, t; }"
        : "=r"(a) : "l"(p));
    return a;
}
__device__ __forceinline__ void sts128(uint32_t addr, uint4 v) {
    asm volatile("st.shared.v4.b32 [%0], {%1,%2,%3,%4};"
                 :: "r"(addr), "r"(v.x), "r"(v.y), "r"(v.z), "r"(v.w) : "memory");
}
__device__ __forceinline__ uint32_t set_gt_h2(uint32_t a, uint32_t b) {
    uint32_t d;
    asm("set.gt.f16x2.f16x2 %0, %1, %2;" : "=r"(d) : "r"(a), "r"(b));
    return d;
}
__device__ __forceinline__ uint32_t mul_h2(uint32_t a, uint32_t b) {
    uint32_t d;
    asm("mul.rn.f16x2 %0, %1, %2;" : "=r"(d) : "r"(a), "r"(b));
    return d;
}
__device__ __forceinline__ uint32_t sub_h2(uint32_t a, uint32_t b) {
    uint32_t d;
    asm("sub.rn.f16x2 %0, %1, %2;" : "=r"(d) : "r"(a), "r"(b));
    return d;
}
__device__ __forceinline__ void ldm4(uint32_t* r, uint32_t addr) {
    asm volatile("ldmatrix.sync.aligned.m8n8.x4.shared.b16 {%0,%1,%2,%3}, [%4];"
                 : "=r"(r[0]), "=r"(r[1]), "=r"(r[2]), "=r"(r[3]) : "r"(addr));
}
__device__ __forceinline__ void ldm2(uint32_t* r, uint32_t addr) {
    asm volatile("ldmatrix.sync.aligned.m8n8.x2.shared.b16 {%0,%1}, [%2];"
                 : "=r"(r[0]), "=r"(r[1]) : "r"(addr));
}
__device__ __forceinline__ void hmma(float* c, const uint32_t* a, const uint32_t* b) {
    asm volatile("mma.sync.aligned.m16n8k16.row.col.f32.f16.f16.f32 "
                 "{%0,%1,%2,%3}, {%4,%5,%6,%7}, {%8,%9}, {%0,%1,%2,%3};"
                 : "+f"(c[0]), "+f"(c[1]), "+f"(c[2]), "+f"(c[3])
                 : "r"(a[0]), "r"(a[1]), "r"(a[2]), "r"(a[3]),
                   "r"(b[0]), "r"(b[1]));
}
__device__ __forceinline__ void cpa16(uint32_t dst, const void* src) {
    asm volatile("cp.async.cg.shared.global [%0], [%1], 16;"
                 :: "r"(dst), "l"(src) : "memory");
}
#define CP_COMMIT() asm volatile("cp.async.commit_group;" ::: "memory")
#define CP_WAIT0()  asm volatile("cp.async.wait_group 0;" ::: "memory")

// ---------------------------------------------------------------------------
// Kernel A: Wh = h @ W   (known-good)
// ---------------------------------------------------------------------------
__global__ __launch_bounds__(256) void gemm_wh(const float* __restrict__ h,
                                               const float* __restrict__ W) {
    __shared__ __align__(16) float h_s[64][64];
    __shared__ __align__(16) float W_s[64][F_OUT];

    const int t = threadIdx.x, lane = t & 31, wid = t >> 5;
    const int ib = wid * 8, i0 = blockIdx.x * 64;
    const int tx = t & 63, ty = t >> 6;

    float acc[8][4] = {};
    for (int k0 = 0; k0 < F_IN; k0 += 64) {
        #pragma unroll
        for (int r = 0; r < 16; r++) {
            int i = ty * 16 + r;
            h_s[tx][(i + tx) & 63] = h[(size_t)(i0 + i) * F_IN + k0 + tx];
        }
        {
            const float4* Wg = reinterpret_cast<const float4*>(W + (size_t)k0 * F_OUT);
            float4* Ws4 = reinterpret_cast<float4*>(&W_s[0][0]);
            #pragma unroll
            for (int r = 0; r < 8; r++) Ws4[t + r * 256] = Wg[t + r * 256];
        }
        __syncthreads();
        #pragma unroll 8
        for (int k = 0; k < 64; k++) {
            float4 wv = reinterpret_cast<float4*>(&W_s[k][0])[lane];
            #pragma unroll
            for (int r = 0; r < 8; r++) {
                float hv = h_s[k][(ib + r + k) & 63];
                acc[r][0] += hv * wv.x; acc[r][1] += hv * wv.y;
                acc[r][2] += hv * wv.z; acc[r][3] += hv * wv.w;
            }
        }
        __syncthreads();
    }
    #pragma unroll
    for (int r = 0; r < 8; r++) {
        int i = i0 + ib + r;
        reinterpret_cast<float4*>(&g_Wh[(size_t)i * F_OUT])[lane] =
            make_float4(acc[r][0], acc[r][1], acc[r][2], acc[r][3]);
    }
}

// ---------------------------------------------------------------------------
// Kernel A2: x=Wh.a1, y=Wh.a2 -> F, Fp, fp16 keys + packed E/Ep fp16x2
// ---------------------------------------------------------------------------
__global__ __launch_bounds__(256) void attn_coeffs(const float* __restrict__ a) {
    const int t = threadIdx.x, lane = t & 31, wid = t >> 5;
    const int i = blockIdx.x * 8 + wid;
    float4 wh = reinterpret_cast<const float4*>(&g_Wh[(size_t)i * F_OUT])[lane];
    float4 a1 = reinterpret_cast<const float4*>(a)[lane];
    float4 a2 = reinterpret_cast<const float4*>(a + F_OUT)[lane];
    float s1 = wh.x * a1.x + wh.y * a1.y + wh.z * a1.z + wh.w * a1.w;
    float s2 = wh.x * a2.x + wh.y * a2.y + wh.z * a2.z + wh.w * a2.w;
    #pragma unroll
    for (int o = 16; o > 0; o >>= 1) {
        s1 += __shfl_xor_sync(0xFFFFFFFFu, s1, o);
        s2 += __shfl_xor_sync(0xFFFFFFFFu, s2, o);
    }
    if (lane == 0) {
        g_F[i]  = expf(s2);
        g_Fp[i] = expf(0.2f * s2);
        g_yhf[i] = __float2half(s2);
        __half nh = __float2half(-s1);
        uint32_t b = (uint32_t)*reinterpret_cast<unsigned short*>(&nh);
        g_nx2[i] = b | (b << 16);
        __half Eh = __float2half(expf(s1));
        uint32_t eb = (uint32_t)*reinterpret_cast<unsigned short*>(&Eh);
        g_Ex2[i] = eb | (eb << 16);
        __half Eph = __float2half(expf(0.2f * s1));
        uint32_t epb = (uint32_t)*reinterpret_cast<unsigned short*>(&Eph);
        g_Epx2[i] = epb | (epb << 16);
    }
}

// ---------------------------------------------------------------------------
// Kernel A3: build B planes [pl][NB n][8192 j] fp16.
//   n<128:  pl0 = F_j*Wh[j][n], pl1 = Fp_j*Wh[j][n]
//   n=128:  pl0 = F_j, pl1 = Fp_j   (denominator column)
//   n=129..135: zero
// ---------------------------------------------------------------------------
__global__ __launch_bounds__(256) void prep_B() {
    __shared__ float s[F_OUT][65];
    __shared__ float sF[64], sFp[64];
    const int t = threadIdx.x;
    const int j0 = blockIdx.x * 64;

    {
        int f4 = (t & 31) * 4;
        int jr = t >> 5;
        #pragma unroll
        for (int p = 0; p < 8; p++) {
            int j = p * 8 + jr;
            float4 v = reinterpret_cast<const float4*>(&g_Wh[(size_t)(j0 + j) * F_OUT])[t & 31];
            s[f4 + 0][j] = v.x; s[f4 + 1][j] = v.y;
            s[f4 + 2][j] = v.z; s[f4 + 3][j] = v.w;
        }
    }
    if (t < 64) { sF[t] = g_F[j0 + t]; sFp[t] = g_Fp[j0 + t]; }
    __syncthreads();

    const int f = t >> 1, half = t & 1;
    #pragma unroll
    for (int q = 0; q < 4; q++) {
        uint32_t b1[4], b0[4];
        #pragma unroll
        for (int k = 0; k < 4; k++) {
            int j = half * 32 + q * 8 + k * 2;
            float w0 = s[f][j], w1 = s[f][j + 1];
            __half2 h1 = __floats2half2_rn(sF[j] * w0,  sF[j + 1] * w1);
            __half2 h0 = __floats2half2_rn(sFp[j] * w0, sFp[j + 1] * w1);
            b1[k] = *reinterpret_cast<uint32_t*>(&h1);
            b0[k] = *reinterpret_cast<uint32_t*>(&h0);
        }
        size_t off = (size_t)f * N_NODES + j0 + half * 32 + q * 8;
        *reinterpret_cast<uint4*>(&g_B[off])                          = make_uint4(b1[0], b1[1], b1[2], b1[3]);
        *reinterpret_cast<uint4*>(&g_B[(size_t)NB * N_NODES + off])   = make_uint4(b0[0], b0[1], b0[2], b0[3]);
    }

    if (t < 64) {
        int j = j0 + t;
        g_B[(size_t)128 * N_NODES + j]        = __float2half(sF[t]);
        g_B[((size_t)NB + 128) * N_NODES + j] = __float2half(sFp[t]);
        __half z = __float2half(0.0f);
        #pragma unroll
        for (int r = 129; r < NB; r++) {
            g_B[(size_t)r * N_NODES + j] = z;
            g_B[((size_t)NB + r) * N_NODES + j] = z;
        }
    }
}

// ---------------------------------------------------------------------------
// Kernel B: merged-accumulator mask-GEMM aggregation.
// CTA (bx, js): rows i in [bx*128,+128), j in [js*4096,+4096).
// A1 = E_i * M1, A0 = Ep_i * M0 (fp16; E baked into masks)
//   -> num = A1@B1 + A0@B0 into ONE fp32 accum set (halves accum regs,
//      enabling M=128 rows/CTA at ~115 regs).
// 512 thr = 16 warps, 4(m) x 4(n): wm = wid&3 (SMSP), wn = wid>>2.
// A single-buffered (masks made+consumed per tile, 2 syncs); B double-buffered.
// den column n=128 via wn==3 warps. Partials to gmem; combine finishes.
// ---------------------------------------------------------------------------
__global__ __launch_bounds__(512, 1) void aggregate(const int* __restrict__ adj) {
    extern __shared__ __align__(1024) char smem[];
    const uint32_t sb = smem_u32(smem);
    // [0, 32768):       A planes  (A1 16KB, A0 16KB) single-buffered
    // [32768, 102400):  B buffers (2 x 2 planes x 17408 B)
    const uint32_t A1 = sb, A0 = sb + 16384;

    const int t = threadIdx.x, lane = t & 31, wid = t >> 5;
    const int wm = wid & 3, wn = wid >> 2;       // 4 x 4 warp grid
    const int i0 = blockIdx.x * MROWS;
    const int js = blockIdx.y;
    const int jbase = js * JCHUNK;

    const int i_my = t >> 2;   // 0..127
    const int jq   = t & 3;    // 16-j chunk

    const uint32_t nx2 = g_nx2[i0 + i_my];
    const uint32_t Ex2 = g_Ex2[i0 + i_my];
    const uint32_t Epx2 = g_Epx2[i0 + i_my];

    float acc[2][4][4] = {};    // [m-tile][n8][frag] merged both branches
    float accd[2][4]   = {};    // den partial (warps wn==3)

    // B cp.async issue for one tile into buffer p (2176 16B-chunks, 512 thr)
    auto issue_b = [&](int j0t, int p) {
        const uint32_t BB = sb + 32768 + p * 34816;
        #pragma unroll
        for (int k = 0; k < 4; k++) {
            int c = k * 512 + t;
            int plane = c / 1088;
            int rem = c - plane * 1088;
            int n = rem >> 3, ch = rem & 7;
            const void* src = &g_B[((size_t)plane * NB + n) * N_NODES + j0t + ch * 8];
            uint32_t dst = BB + plane * 17408 + n * 128 + ((ch ^ (n & 7)) << 4);
            cpa16(dst, src);
        }
        if (t < 128) {   // leftover: plane 1 tail
            int rem = 960 + t;
            int n = rem >> 3, ch = rem & 7;
            const void* src = &g_B[((size_t)NB + n) * N_NODES + j0t + ch * 8];
            uint32_t dst = BB + 17408 + n * 128 + ((ch ^ (n & 7)) << 4);
            cpa16(dst, src);
        }
    };

    // prologue: adj tile 0 prefetch + B tile 0 cp.async
    int4 adjv[4];
    {
        const int4* ap = reinterpret_cast<const int4*>(
            adj + (size_t)(i0 + i_my) * N_NODES + jbase + jq * 16);
        #pragma unroll
        for (int q = 0; q < 4; q++) adjv[q] = ap[q];
    }
    issue_b(jbase, 0);
    CP_COMMIT();

    for (int tl = 0; tl < NTILES; tl++) {
        const int p = tl & 1;
        const int j0 = jbase + tl * 64;
        const uint32_t BB = sb + 32768 + p * 34816;

        CP_WAIT0();   // this tile's B planes have landed

        // ---- build scaled masks (each thread: 16 j's for one i-row) ----
        {
            const uint32_t* yb = reinterpret_cast<const uint32_t*>(g_yhf + j0 + jq * 16);
            uint32_t m1r[8], m0r[8];
            #pragma unroll
            for (int q = 0; q < 4; q++) {
                int4 av = adjv[q];
                uint32_t y01 = yb[2 * q], y23 = yb[2 * q + 1];
                uint32_t u01 = (uint32_t)av.x | ((uint32_t)av.y << 16);
                uint32_t u23 = (uint32_t)av.z | ((uint32_t)av.w << 16);
                uint32_t a01 = u01 * 0x3C00u, a23 = u23 * 0x3C00u;  // fp16 1.0 per set half
                uint32_t p01 = set_gt_h2(y01, nx2), p23 = set_gt_h2(y23, nx2);
                uint32_t q01 = mul_h2(a01, p01), q23 = mul_h2(a23, p23);
                m1r[2 * q]     = mul_h2(q01, Ex2);
                m1r[2 * q + 1] = mul_h2(q23, Ex2);
                m0r[2 * q]     = mul_h2(sub_h2(a01, q01), Epx2);
                m0r[2 * q + 1] = mul_h2(sub_h2(a23, q23), Epx2);
            }
            uint32_t rowb = (uint32_t)i_my * 128;
            uint32_t so0 = (uint32_t)(((2 * jq)     ^ (i_my & 7)) << 4);
            uint32_t so1 = (uint32_t)(((2 * jq + 1) ^ (i_my & 7)) << 4);
            sts128(A1 + rowb + so0, make_uint4(m1r[0], m1r[1], m1r[2], m1r[3]));
            sts128(A1 + rowb + so1, make_uint4(m1r[4], m1r[5], m1r[6], m1r[7]));
            sts128(A0 + rowb + so0, make_uint4(m0r[0], m0r[1], m0r[2], m0r[3]));
            sts128(A0 + rowb + so1, make_uint4(m0r[4], m0r[5], m0r[6], m0r[7]));
        }
        __syncthreads();

        // ---- prefetch next tile (overlaps compute below) ----
        if (tl + 1 < NTILES) {
            const int jn = j0 + 64;
            const int4* ap = reinterpret_cast<const int4*>(
                adj + (size_t)(i0 + i_my) * N_NODES + jn + jq * 16);
            #pragma unroll
            for (int q = 0; q < 4; q++) adjv[q] = ap[q];
            issue_b(jn, (tl + 1) & 1);
        }
        CP_COMMIT();

        // ---- compute: 4 k-steps ----
        #pragma unroll
        for (int ks = 0; ks < 4; ks++) {
            uint32_t am1[2][4], am0[2][4];
            #pragma unroll
            for (int mt = 0; mt < 2; mt++) {
                uint32_t arow = (uint32_t)(wm * 32 + mt * 16
                                           + (lane & 7) + ((lane >> 3) & 1) * 8);
                uint32_t ach = (uint32_t)(ks * 2 + (lane >> 4));
                uint32_t aoff = arow * 128 + ((ach ^ (arow & 7)) << 4);
                ldm4(am1[mt], A1 + aoff);
                ldm4(am0[mt], A0 + aoff);
            }

            uint32_t bch = (uint32_t)(ks * 2 + ((lane >> 3) & 1));
            #pragma unroll
            for (int nh = 0; nh < 2; nh++) {   // two 16-col halves of warp's 32
                uint32_t nrow = (uint32_t)(wn * 4 + nh * 2 + (lane >> 4)) * 8 + (lane & 7);
                uint32_t boff = nrow * 128 + ((bch ^ (nrow & 7)) << 4);
                uint32_t b1f[4], b0f[4];
                ldm4(b1f, BB + boff);
                ldm4(b0f, BB + 17408 + boff);
                #pragma unroll
                for (int mt = 0; mt < 2; mt++) {
                    #pragma unroll
                    for (int ns = 0; ns < 2; ns++) {
                        hmma(acc[mt][nh * 2 + ns], am1[mt], b1f + 2 * ns);
                        hmma(acc[mt][nh * 2 + ns], am0[mt], b0f + 2 * ns);
                    }
                }
            }

            // den column n=128: warps wn==3, both planes into accd
            if (wn == 3) {
                uint32_t dnrow = 128 + (lane & 7);
                uint32_t dsw = ((bch ^ (dnrow & 7)) << 4);
                uint32_t bd1[2], bd0[2];
                ldm2(bd1, BB + dnrow * 128 + dsw);
                ldm2(bd0, BB + 17408 + dnrow * 128 + dsw);
                #pragma unroll
                for (int mt = 0; mt < 2; mt++) {
                    hmma(accd[mt], am1[mt], bd1);
                    hmma(accd[mt], am0[mt], bd0);
                }
            }
        }
        __syncthreads();   // all A reads done before next tile's mask writes
    }

    // ---- store partials (E/Ep already baked in) ----
    #pragma unroll
    for (int mt = 0; mt < 2; mt++) {
        int rA = wm * 32 + mt * 16 + (lane >> 2);
        int rB = rA + 8;
        #pragma unroll
        for (int ns = 0; ns < 4; ns++) {
            int n = wn * 32 + ns * 8 + (lane & 3) * 2;
            *reinterpret_cast<float2*>(&g_pnum[js][i0 + rA][n]) =
                make_float2(acc[mt][ns][0], acc[mt][ns][1]);
            *reinterpret_cast<float2*>(&g_pnum[js][i0 + rB][n]) =
                make_float2(acc[mt][ns][2], acc[mt][ns][3]);
        }
        if (wn == 3 && (lane & 3) == 0) {
            g_pden[js][i0 + rA] = accd[mt][0];
            g_pden[js][i0 + rB] = accd[mt][2];
        }
    }
}

// ---------------------------------------------------------------------------
// Kernel C: combine j-split partials, normalize, ELU.
// ---------------------------------------------------------------------------
__global__ __launch_bounds__(256) void combine(float* __restrict__ out) {
    const int idx = blockIdx.x * 256 + threadIdx.x;
    const int i = idx >> 7;
    const int f = idx & (F_OUT - 1);
    float num = g_pnum[0][i][f] + g_pnum[1][i][f];
    float den = g_pden[0][i] + g_pden[1][i];
    float v = num / den;
    out[idx] = (v > 0.0f) ? v : expm1f(v);
}

// ---------------------------------------------------------------------------
extern "C" void kernel_launch(void* const* d_in, const int* in_sizes, int n_in,
                              void* d_out, int out_size) {
    const float* h   = (const float*)d_in[0];
    const int*   adj = (const int*)d_in[1];
    const float* W   = (const float*)d_in[2];
    const float* a   = (const float*)d_in[3];
    float* out = (float*)d_out;

    const int AGG_SMEM = 102400;
    cudaFuncSetAttribute(aggregate, cudaFuncAttributeMaxDynamicSharedMemorySize, AGG_SMEM);

    gemm_wh<<<N_NODES / 64, 256>>>(h, W);
    attn_coeffs<<<N_NODES / 8, 256>>>(a);
    prep_B<<<N_NODES / 64, 256>>>();
    aggregate<<<dim3(N_NODES / MROWS, JSPLIT), 512, AGG_SMEM>>>(adj);
    combine<<<(N_NODES * F_OUT) / 256, 256>>>(out);
}

// round 17
// speedup vs baseline: 1.0256x; 1.0256x over previous
#include <cuda_runtime.h>
#include <cuda_bf16.h>
#include <cuda_fp16.h>
#include <cstdint>
#include <math.h>

#define N_NODES 8192
#define F_IN    256
#define F_OUT   128
#define NB      136            // GEMM N: 128 feats + den col(128) + 7 zero pad
#define JSPLIT  2
#define JCHUNK  (N_NODES / JSPLIT)   // 4096
#define NTILES  (JCHUNK / 64)        // 64 k-tiles per CTA
#define MROWS   128                  // rows per CTA

// ------------------------------ device scratch ------------------------------
__device__ float    g_Wh[N_NODES * F_OUT];        // 4 MB
__device__ float    g_F[N_NODES], g_Fp[N_NODES];  // e^y, e^{0.2y}
__device__ __half   g_yhf[N_NODES];               // fp16(y_j)
__device__ uint32_t g_nx2[N_NODES];               // {fp16(-x_i)} x2
__device__ uint32_t g_Ex2[N_NODES];               // {fp16(e^{x_i})} x2
__device__ uint32_t g_Epx2[N_NODES];              // {fp16(e^{0.2 x_i})} x2
// B planes [pl][NB][8192] fp16; pl: 0 = B1 = F*Wh, 1 = B0 = Fp*Wh
__device__ __half   g_B[2 * NB * N_NODES];        // 4.5 MB
__device__ float    g_pnum[JSPLIT][N_NODES][F_OUT];  // 8 MB partial numerators
__device__ float    g_pden[JSPLIT][N_NODES];

// ------------------------------ asm helpers ---------------------------------
__device__ __forceinline__ uint32_t smem_u32(const void* p) {
    uint32_t a;
    asm("{ .reg .u64 t; cvta.to.shared.u64 t, %1; cvt.u32.u64 %0, t; }"
        : "=r"(a) : "l"(p));
    return a;
}
__device__ __forceinline__ void sts128(uint32_t addr, uint4 v) {
    asm volatile("st.shared.v4.b32 [%0], {%1,%2,%3,%4};"
                 :: "r"(addr), "r"(v.x), "r"(v.y), "r"(v.z), "r"(v.w) : "memory");
}
__device__ __forceinline__ uint32_t set_gt_h2(uint32_t a, uint32_t b) {
    uint32_t d;
    asm("set.gt.f16x2.f16x2 %0, %1, %2;" : "=r"(d) : "r"(a), "r"(b));
    return d;
}
__device__ __forceinline__ uint32_t mul_h2(uint32_t a, uint32_t b) {
    uint32_t d;
    asm("mul.rn.f16x2 %0, %1, %2;" : "=r"(d) : "r"(a), "r"(b));
    return d;
}
__device__ __forceinline__ uint32_t sub_h2(uint32_t a, uint32_t b) {
    uint32_t d;
    asm("sub.rn.f16x2 %0, %1, %2;" : "=r"(d) : "r"(a), "r"(b));
    return d;
}
__device__ __forceinline__ void ldm4(uint32_t* r, uint32_t addr) {
    asm volatile("ldmatrix.sync.aligned.m8n8.x4.shared.b16 {%0,%1,%2,%3}, [%4];"
                 : "=r"(r[0]), "=r"(r[1]), "=r"(r[2]), "=r"(r[3]) : "r"(addr));
}
__device__ __forceinline__ void ldm2(uint32_t* r, uint32_t addr) {
    asm volatile("ldmatrix.sync.aligned.m8n8.x2.shared.b16 {%0,%1}, [%2];"
                 : "=r"(r[0]), "=r"(r[1]) : "r"(addr));
}
__device__ __forceinline__ void hmma(float* c, const uint32_t* a, const uint32_t* b) {
    asm volatile("mma.sync.aligned.m16n8k16.row.col.f32.f16.f16.f32 "
                 "{%0,%1,%2,%3}, {%4,%5,%6,%7}, {%8,%9}, {%0,%1,%2,%3};"
                 : "+f"(c[0]), "+f"(c[1]), "+f"(c[2]), "+f"(c[3])
                 : "r"(a[0]), "r"(a[1]), "r"(a[2]), "r"(a[3]),
                   "r"(b[0]), "r"(b[1]));
}
__device__ __forceinline__ void cpa16(uint32_t dst, const void* src) {
    asm volatile("cp.async.cg.shared.global [%0], [%1], 16;"
                 :: "r"(dst), "l"(src) : "memory");
}
#define CP_COMMIT() asm volatile("cp.async.commit_group;" ::: "memory")
#define CP_WAIT0()  asm volatile("cp.async.wait_group 0;" ::: "memory")
#define CP_WAIT1()  asm volatile("cp.async.wait_group 1;" ::: "memory")

// ---------------------------------------------------------------------------
// Kernel A: Wh = h @ W.  32-row tiles -> grid 256 (was 128 = 1 CTA/SM,
// latency-bound at issue 46%).
// ---------------------------------------------------------------------------
__global__ __launch_bounds__(256) void gemm_wh(const float* __restrict__ h,
                                               const float* __restrict__ W) {
    __shared__ __align__(16) float h_s[64][32];   // [k][i], rotated columns
    __shared__ __align__(16) float W_s[64][F_OUT];

    const int t = threadIdx.x, lane = t & 31, wid = t >> 5;
    const int ib = wid * 4, i0 = blockIdx.x * 32;
    const int tx = t & 63, ty = t >> 6;

    float acc[4][4] = {};
    for (int k0 = 0; k0 < F_IN; k0 += 64) {
        #pragma unroll
        for (int r = 0; r < 8; r++) {
            int i = ty * 8 + r;
            h_s[tx][(i + tx) & 31] = h[(size_t)(i0 + i) * F_IN + k0 + tx];
        }
        {
            const float4* Wg = reinterpret_cast<const float4*>(W + (size_t)k0 * F_OUT);
            float4* Ws4 = reinterpret_cast<float4*>(&W_s[0][0]);
            #pragma unroll
            for (int r = 0; r < 8; r++) Ws4[t + r * 256] = Wg[t + r * 256];
        }
        __syncthreads();
        #pragma unroll 8
        for (int k = 0; k < 64; k++) {
            float4 wv = reinterpret_cast<float4*>(&W_s[k][0])[lane];
            #pragma unroll
            for (int r = 0; r < 4; r++) {
                float hv = h_s[k][(ib + r + k) & 31];
                acc[r][0] += hv * wv.x; acc[r][1] += hv * wv.y;
                acc[r][2] += hv * wv.z; acc[r][3] += hv * wv.w;
            }
        }
        __syncthreads();
    }
    #pragma unroll
    for (int r = 0; r < 4; r++) {
        int i = i0 + ib + r;
        reinterpret_cast<float4*>(&g_Wh[(size_t)i * F_OUT])[lane] =
            make_float4(acc[r][0], acc[r][1], acc[r][2], acc[r][3]);
    }
}

// ---------------------------------------------------------------------------
// Kernel A2: x=Wh.a1, y=Wh.a2 -> F, Fp, fp16 keys + packed E/Ep fp16x2
// ---------------------------------------------------------------------------
__global__ __launch_bounds__(256) void attn_coeffs(const float* __restrict__ a) {
    const int t = threadIdx.x, lane = t & 31, wid = t >> 5;
    const int i = blockIdx.x * 8 + wid;
    float4 wh = reinterpret_cast<const float4*>(&g_Wh[(size_t)i * F_OUT])[lane];
    float4 a1 = reinterpret_cast<const float4*>(a)[lane];
    float4 a2 = reinterpret_cast<const float4*>(a + F_OUT)[lane];
    float s1 = wh.x * a1.x + wh.y * a1.y + wh.z * a1.z + wh.w * a1.w;
    float s2 = wh.x * a2.x + wh.y * a2.y + wh.z * a2.z + wh.w * a2.w;
    #pragma unroll
    for (int o = 16; o > 0; o >>= 1) {
        s1 += __shfl_xor_sync(0xFFFFFFFFu, s1, o);
        s2 += __shfl_xor_sync(0xFFFFFFFFu, s2, o);
    }
    if (lane == 0) {
        g_F[i]  = expf(s2);
        g_Fp[i] = expf(0.2f * s2);
        g_yhf[i] = __float2half(s2);
        __half nh = __float2half(-s1);
        uint32_t b = (uint32_t)*reinterpret_cast<unsigned short*>(&nh);
        g_nx2[i] = b | (b << 16);
        __half Eh = __float2half(expf(s1));
        uint32_t eb = (uint32_t)*reinterpret_cast<unsigned short*>(&Eh);
        g_Ex2[i] = eb | (eb << 16);
        __half Eph = __float2half(expf(0.2f * s1));
        uint32_t epb = (uint32_t)*reinterpret_cast<unsigned short*>(&Eph);
        g_Epx2[i] = epb | (epb << 16);
    }
}

// ---------------------------------------------------------------------------
// Kernel A3: build B planes [pl][NB n][8192 j] fp16.
// ---------------------------------------------------------------------------
__global__ __launch_bounds__(256) void prep_B() {
    __shared__ float s[F_OUT][65];
    __shared__ float sF[64], sFp[64];
    const int t = threadIdx.x;
    const int j0 = blockIdx.x * 64;

    {
        int f4 = (t & 31) * 4;
        int jr = t >> 5;
        #pragma unroll
        for (int p = 0; p < 8; p++) {
            int j = p * 8 + jr;
            float4 v = reinterpret_cast<const float4*>(&g_Wh[(size_t)(j0 + j) * F_OUT])[t & 31];
            s[f4 + 0][j] = v.x; s[f4 + 1][j] = v.y;
            s[f4 + 2][j] = v.z; s[f4 + 3][j] = v.w;
        }
    }
    if (t < 64) { sF[t] = g_F[j0 + t]; sFp[t] = g_Fp[j0 + t]; }
    __syncthreads();

    const int f = t >> 1, half = t & 1;
    #pragma unroll
    for (int q = 0; q < 4; q++) {
        uint32_t b1[4], b0[4];
        #pragma unroll
        for (int k = 0; k < 4; k++) {
            int j = half * 32 + q * 8 + k * 2;
            float w0 = s[f][j], w1 = s[f][j + 1];
            __half2 h1 = __floats2half2_rn(sF[j] * w0,  sF[j + 1] * w1);
            __half2 h0 = __floats2half2_rn(sFp[j] * w0, sFp[j + 1] * w1);
            b1[k] = *reinterpret_cast<uint32_t*>(&h1);
            b0[k] = *reinterpret_cast<uint32_t*>(&h0);
        }
        size_t off = (size_t)f * N_NODES + j0 + half * 32 + q * 8;
        *reinterpret_cast<uint4*>(&g_B[off])                        = make_uint4(b1[0], b1[1], b1[2], b1[3]);
        *reinterpret_cast<uint4*>(&g_B[(size_t)NB * N_NODES + off]) = make_uint4(b0[0], b0[1], b0[2], b0[3]);
    }

    if (t < 64) {
        int j = j0 + t;
        g_B[(size_t)128 * N_NODES + j]        = __float2half(sF[t]);
        g_B[((size_t)NB + 128) * N_NODES + j] = __float2half(sFp[t]);
        __half z = __float2half(0.0f);
        #pragma unroll
        for (int r = 129; r < NB; r++) {
            g_B[(size_t)r * N_NODES + j] = z;
            g_B[((size_t)NB + r) * N_NODES + j] = z;
        }
    }
}

// ---------------------------------------------------------------------------
// Kernel B: software-pipelined merged-accumulator mask-GEMM aggregation.
// Per iteration: build masks for tile t+1 into A[p^1], THEN compute GEMM
// tile t from A[p] / B[p]; ONE __syncthreads per tile. ALU (mask) and
// tensor (HMMA) phases overlap across warps; adj LDG issued a tile ahead;
// B double-buffered via cp.async with wait_group 1.
// ---------------------------------------------------------------------------
__global__ __launch_bounds__(512, 1) void aggregate(const int* __restrict__ adj) {
    extern __shared__ __align__(1024) char smem[];
    const uint32_t sb = smem_u32(smem);
    // [0, 65536):        A buffers: p in {0,1} -> A1 at p*32768, A0 at +16384
    // [65536, 135168):   B buffers: 2 x 2 planes x 17408 B

    const int t = threadIdx.x, lane = t & 31, wid = t >> 5;
    const int wm = wid & 3, wn = wid >> 2;       // 4 x 4 warp grid
    const int i0 = blockIdx.x * MROWS;
    const int js = blockIdx.y;
    const int jbase = js * JCHUNK;

    const int i_my = t >> 2;   // 0..127
    const int jq   = t & 3;    // 16-j chunk

    const uint32_t nx2  = g_nx2[i0 + i_my];
    const uint32_t Ex2  = g_Ex2[i0 + i_my];
    const uint32_t Epx2 = g_Epx2[i0 + i_my];

    float acc[2][4][4] = {};    // merged both branches
    float accd[2][4]   = {};    // den partial (warps wn==3)

    int4 adjv[4];
    auto load_adj = [&](int j0t) {
        const int4* ap = reinterpret_cast<const int4*>(
            adj + (size_t)(i0 + i_my) * N_NODES + j0t + jq * 16);
        #pragma unroll
        for (int q = 0; q < 4; q++) adjv[q] = ap[q];
    };

    auto issue_b = [&](int j0t, int p) {
        const uint32_t BB = sb + 65536 + p * 34816;
        #pragma unroll
        for (int k = 0; k < 4; k++) {
            int c = k * 512 + t;
            int plane = c / 1088;
            int rem = c - plane * 1088;
            int n = rem >> 3, ch = rem & 7;
            const void* src = &g_B[((size_t)plane * NB + n) * N_NODES + j0t + ch * 8];
            uint32_t dst = BB + plane * 17408 + n * 128 + ((ch ^ (n & 7)) << 4);
            cpa16(dst, src);
        }
        if (t < 128) {   // leftover: plane 1 tail
            int rem = 960 + t;
            int n = rem >> 3, ch = rem & 7;
            const void* src = &g_B[((size_t)NB + n) * N_NODES + j0t + ch * 8];
            uint32_t dst = BB + 17408 + n * 128 + ((ch ^ (n & 7)) << 4);
            cpa16(dst, src);
        }
    };

    auto build_masks = [&](int j0t, int p) {   // into buffer p
        const uint32_t A1b = sb + p * 32768;
        const uint32_t A0b = A1b + 16384;
        const uint32_t* yb = reinterpret_cast<const uint32_t*>(g_yhf + j0t + jq * 16);
        uint32_t m1r[8], m0r[8];
        #pragma unroll
        for (int q = 0; q < 4; q++) {
            int4 av = adjv[q];
            uint32_t y01 = yb[2 * q], y23 = yb[2 * q + 1];
            uint32_t u01 = (uint32_t)av.x | ((uint32_t)av.y << 16);
            uint32_t u23 = (uint32_t)av.z | ((uint32_t)av.w << 16);
            uint32_t a01 = u01 * 0x3C00u, a23 = u23 * 0x3C00u;  // fp16 1.0 per set half
            uint32_t p01 = set_gt_h2(y01, nx2), p23 = set_gt_h2(y23, nx2);
            uint32_t q01 = mul_h2(a01, p01), q23 = mul_h2(a23, p23);
            m1r[2 * q]     = mul_h2(q01, Ex2);
            m1r[2 * q + 1] = mul_h2(q23, Ex2);
            m0r[2 * q]     = mul_h2(sub_h2(a01, q01), Epx2);
            m0r[2 * q + 1] = mul_h2(sub_h2(a23, q23), Epx2);
        }
        uint32_t rowb = (uint32_t)i_my * 128;
        uint32_t so0 = (uint32_t)(((2 * jq)     ^ (i_my & 7)) << 4);
        uint32_t so1 = (uint32_t)(((2 * jq + 1) ^ (i_my & 7)) << 4);
        sts128(A1b + rowb + so0, make_uint4(m1r[0], m1r[1], m1r[2], m1r[3]));
        sts128(A1b + rowb + so1, make_uint4(m1r[4], m1r[5], m1r[6], m1r[7]));
        sts128(A0b + rowb + so0, make_uint4(m0r[0], m0r[1], m0r[2], m0r[3]));
        sts128(A0b + rowb + so1, make_uint4(m0r[4], m0r[5], m0r[6], m0r[7]));
    };

    // ---- prologue: B(0) in flight, masks(0) built, adj(1) prefetched ----
    issue_b(jbase, 0);
    CP_COMMIT();
    load_adj(jbase);
    build_masks(jbase, 0);
    if (NTILES > 1) load_adj(jbase + 64);
    __syncthreads();

    for (int tl = 0; tl < NTILES; tl++) {
        const int p = tl & 1;
        const uint32_t A1c = sb + p * 32768;
        const uint32_t A0c = A1c + 16384;
        const uint32_t BB = sb + 65536 + p * 34816;

        // ---- pipeline stage: next tile's B + masks ----
        if (tl + 1 < NTILES) {
            issue_b(jbase + (tl + 1) * 64, p ^ 1);
            CP_COMMIT();
            build_masks(jbase + (tl + 1) * 64, p ^ 1);
        }
        if (tl + 2 < NTILES) load_adj(jbase + (tl + 2) * 64);

        if (tl + 1 < NTILES) { CP_WAIT1(); } else { CP_WAIT0(); }  // B[p] landed

        // ---- compute tile tl: 4 k-steps ----
        #pragma unroll
        for (int ks = 0; ks < 4; ks++) {
            uint32_t am1[2][4], am0[2][4];
            #pragma unroll
            for (int mt = 0; mt < 2; mt++) {
                uint32_t arow = (uint32_t)(wm * 32 + mt * 16
                                           + (lane & 7) + ((lane >> 3) & 1) * 8);
                uint32_t ach = (uint32_t)(ks * 2 + (lane >> 4));
                uint32_t aoff = arow * 128 + ((ach ^ (arow & 7)) << 4);
                ldm4(am1[mt], A1c + aoff);
                ldm4(am0[mt], A0c + aoff);
            }

            uint32_t bch = (uint32_t)(ks * 2 + ((lane >> 3) & 1));
            #pragma unroll
            for (int nh = 0; nh < 2; nh++) {
                uint32_t nrow = (uint32_t)(wn * 4 + nh * 2 + (lane >> 4)) * 8 + (lane & 7);
                uint32_t boff = nrow * 128 + ((bch ^ (nrow & 7)) << 4);
                uint32_t b1f[4], b0f[4];
                ldm4(b1f, BB + boff);
                ldm4(b0f, BB + 17408 + boff);
                #pragma unroll
                for (int mt = 0; mt < 2; mt++) {
                    #pragma unroll
                    for (int ns = 0; ns < 2; ns++) {
                        hmma(acc[mt][nh * 2 + ns], am1[mt], b1f + 2 * ns);
                        hmma(acc[mt][nh * 2 + ns], am0[mt], b0f + 2 * ns);
                    }
                }
            }

            if (wn == 3) {   // den column n=128
                uint32_t dnrow = 128 + (lane & 7);
                uint32_t dsw = ((bch ^ (dnrow & 7)) << 4);
                uint32_t bd1[2], bd0[2];
                ldm2(bd1, BB + dnrow * 128 + dsw);
                ldm2(bd0, BB + 17408 + dnrow * 128 + dsw);
                #pragma unroll
                for (int mt = 0; mt < 2; mt++) {
                    hmma(accd[mt], am1[mt], bd1);
                    hmma(accd[mt], am0[mt], bd0);
                }
            }
        }
        __syncthreads();   // A[p] reads done; A[p^1] writes visible for next tile
    }

    // ---- store partials (E/Ep already baked in) ----
    #pragma unroll
    for (int mt = 0; mt < 2; mt++) {
        int rA = wm * 32 + mt * 16 + (lane >> 2);
        int rB = rA + 8;
        #pragma unroll
        for (int ns = 0; ns < 4; ns++) {
            int n = wn * 32 + ns * 8 + (lane & 3) * 2;
            *reinterpret_cast<float2*>(&g_pnum[js][i0 + rA][n]) =
                make_float2(acc[mt][ns][0], acc[mt][ns][1]);
            *reinterpret_cast<float2*>(&g_pnum[js][i0 + rB][n]) =
                make_float2(acc[mt][ns][2], acc[mt][ns][3]);
        }
        if (wn == 3 && (lane & 3) == 0) {
            g_pden[js][i0 + rA] = accd[mt][0];
            g_pden[js][i0 + rB] = accd[mt][2];
        }
    }
}

// ---------------------------------------------------------------------------
// Kernel C: combine j-split partials, normalize, ELU.
// ---------------------------------------------------------------------------
__global__ __launch_bounds__(256) void combine(float* __restrict__ out) {
    const int idx = blockIdx.x * 256 + threadIdx.x;
    const int i = idx >> 7;
    const int f = idx & (F_OUT - 1);
    float num = g_pnum[0][i][f] + g_pnum[1][i][f];
    float den = g_pden[0][i] + g_pden[1][i];
    float v = num / den;
    out[idx] = (v > 0.0f) ? v : expm1f(v);
}

// ---------------------------------------------------------------------------
extern "C" void kernel_launch(void* const* d_in, const int* in_sizes, int n_in,
                              void* d_out, int out_size) {
    const float* h   = (const float*)d_in[0];
    const int*   adj = (const int*)d_in[1];
    const float* W   = (const float*)d_in[2];
    const float* a   = (const float*)d_in[3];
    float* out = (float*)d_out;

    const int AGG_SMEM = 135168;
    cudaFuncSetAttribute(aggregate, cudaFuncAttributeMaxDynamicSharedMemorySize, AGG_SMEM);

    gemm_wh<<<N_NODES / 32, 256>>>(h, W);
    attn_coeffs<<<N_NODES / 8, 256>>>(a);
    prep_B<<<N_NODES / 64, 256>>>();
    aggregate<<<dim3(N_NODES / MROWS, JSPLIT), 512, AGG_SMEM>>>(adj);
    combine<<<(N_NODES * F_OUT) / 256, 256>>>(out);
}